// round 4
// baseline (speedup 1.0000x reference)
#include <cuda_runtime.h>

// Torch_SINDy streaming kernel, R4: persistent grid-stride.
// R3: DRAM=75%, issue=27.8% (memory-parked), grid=4096 one-shot blocks
// -> ~4-5 waves, each re-paying wave transition + coeff-load prologue.
// Fix: 912 persistent blocks (6/SM x 152 SM), loop over full chunks,
// unguarded MLP=8 front-batched loads, streaming cache hints.

#define ITEMS 8
#define THREADS 256
#define CHUNK (THREADS * ITEMS)   // 2048 rows per chunk

__device__ __forceinline__ float sindy_row(float4 v, const float* c) {
    float u  = v.x;
    float u2 = u * u;
    float u3 = u2 * u;
    float y = v.y, z = v.z, w = v.w;
    float r = u * c[0] + u2 * c[1] + u3 * c[2]
            + y * c[3] + z * c[4] + w * c[5];
    r += y * (u * c[6]  + u2 * c[7]  + u3 * c[8]);
    r += z * (u * c[9]  + u2 * c[10] + u3 * c[11]);
    r += w * (u * c[12] + u2 * c[13] + u3 * c[14]);
    return r;
}

__device__ __forceinline__ void load_coeffs(const float* __restrict__ coeff,
                                            const float* __restrict__ base,
                                            float* c) {
    const float4* c4 = (const float4*)coeff;
    const float4* b4 = (const float4*)base;
#pragma unroll
    for (int q = 0; q < 3; ++q) {
        float4 cv = __ldg(&c4[q]);
        float4 bv = __ldg(&b4[q]);
        c[q*4+0] = cv.x * bv.x;
        c[q*4+1] = cv.y * bv.y;
        c[q*4+2] = cv.z * bv.z;
        c[q*4+3] = cv.w * bv.w;
    }
#pragma unroll
    for (int q = 12; q < 15; ++q)
        c[q] = __ldg(&coeff[q]) * __ldg(&base[q]);
}

// Persistent kernel: loops over full CHUNK-row tiles, unguarded.
__global__ void __launch_bounds__(THREADS, 6)
sindy_persistent(const float4* __restrict__ big_u,
                 const float*  __restrict__ coeff,
                 const float*  __restrict__ base,
                 float*        __restrict__ out,
                 int n_chunks) {
    float c[15];
    load_coeffs(coeff, base, c);

    for (int chunk = blockIdx.x; chunk < n_chunks; chunk += gridDim.x) {
        int base_i = chunk * CHUNK + threadIdx.x;

        float4 v[ITEMS];
#pragma unroll
        for (int k = 0; k < ITEMS; ++k)
            v[k] = __ldcs(&big_u[base_i + k * THREADS]);

#pragma unroll
        for (int k = 0; k < ITEMS; ++k)
            __stcs(&out[base_i + k * THREADS], sindy_row(v[k], c));
    }
}

// Guarded tail for rows beyond the last full chunk (unused when n % CHUNK == 0).
__global__ void __launch_bounds__(THREADS)
sindy_tail(const float4* __restrict__ big_u,
           const float*  __restrict__ coeff,
           const float*  __restrict__ base,
           float*        __restrict__ out,
           int start, int n) {
    float c[15];
    load_coeffs(coeff, base, c);
    int i = start + blockIdx.x * THREADS + threadIdx.x;
    if (i < n) {
        float4 v = __ldcs(&big_u[i]);
        __stcs(&out[i], sindy_row(v, c));
    }
}

extern "C" void kernel_launch(void* const* d_in, const int* in_sizes, int n_in,
                              void* d_out, int out_size) {
    const float4* big_u = (const float4*)d_in[0];   // [N,4] f32
    const float*  coeff = (const float*)d_in[1];    // [15]  f32
    const float*  base  = (const float*)d_in[2];    // [15]  f32
    float* out = (float*)d_out;                     // [N,1] f32

    int n = in_sizes[0] / 4;   // rows
    int n_chunks = n / CHUNK;

    // 152 SMs x 6 resident blocks (regs ~40, 8 warps/block)
    int grid = 152 * 6;
    if (grid > n_chunks) grid = n_chunks > 0 ? n_chunks : 1;

    if (n_chunks > 0)
        sindy_persistent<<<grid, THREADS>>>(big_u, coeff, base, out, n_chunks);

    int tail_start = n_chunks * CHUNK;
    int tail = n - tail_start;
    if (tail > 0) {
        int tblocks = (tail + THREADS - 1) / THREADS;
        sindy_tail<<<tblocks, THREADS>>>(big_u, coeff, base, out, tail_start, n);
    }
}

// round 5
// speedup vs baseline: 1.0468x; 1.0468x over previous
#include <cuda_runtime.h>

// Torch_SINDy streaming kernel, R5.
// R4 lesson: persistent loop regressed (per-CTA serialization); one-shot
// grid's cross-CTA MLP is what saturates HBM. R5 = R3 structure with
// MLP=16 front-batched loads + float4-packed stores (4 rows/thread/group).

#define THREADS 256
#define GROUPS 4                    // 4 output float4 stores per thread
#define ROWS_PER_GROUP 4            // consecutive rows -> one STG.128
#define CHUNK (THREADS * GROUPS * ROWS_PER_GROUP)   // 4096 rows per block

__device__ __forceinline__ float sindy_row(float4 v, const float* c) {
    float u  = v.x;
    float u2 = u * u;
    float u3 = u2 * u;
    float y = v.y, z = v.z, w = v.w;
    float r = u * c[0] + u2 * c[1] + u3 * c[2]
            + y * c[3] + z * c[4] + w * c[5];
    r += y * (u * c[6]  + u2 * c[7]  + u3 * c[8]);
    r += z * (u * c[9]  + u2 * c[10] + u3 * c[11]);
    r += w * (u * c[12] + u2 * c[13] + u3 * c[14]);
    return r;
}

__device__ __forceinline__ void load_coeffs(const float* __restrict__ coeff,
                                            const float* __restrict__ base,
                                            float* c) {
    const float4* c4 = (const float4*)coeff;
    const float4* b4 = (const float4*)base;
#pragma unroll
    for (int q = 0; q < 3; ++q) {
        float4 cv = __ldg(&c4[q]);
        float4 bv = __ldg(&b4[q]);
        c[q*4+0] = cv.x * bv.x;
        c[q*4+1] = cv.y * bv.y;
        c[q*4+2] = cv.z * bv.z;
        c[q*4+3] = cv.w * bv.w;
    }
#pragma unroll
    for (int q = 12; q < 15; ++q)
        c[q] = __ldg(&coeff[q]) * __ldg(&base[q]);
}

// Exact path: grid covers n exactly, no guards.
// Thread t, group g owns rows: blk*CHUNK + g*THREADS*4 + t*4 + [0..3]
// -> 16 front-batched LDG.128 (MLP=16), then 4 STG.128.
__global__ void __launch_bounds__(THREADS)
sindy_kernel_exact(const float4* __restrict__ big_u,
                   const float*  __restrict__ coeff,
                   const float*  __restrict__ base,
                   float4*       __restrict__ out4) {
    float c[15];
    load_coeffs(coeff, base, c);

    int blk_row = blockIdx.x * CHUNK;

    float4 v[GROUPS][ROWS_PER_GROUP];
#pragma unroll
    for (int g = 0; g < GROUPS; ++g) {
        int row0 = blk_row + g * (THREADS * ROWS_PER_GROUP) + threadIdx.x * ROWS_PER_GROUP;
#pragma unroll
        for (int j = 0; j < ROWS_PER_GROUP; ++j)
            v[g][j] = __ldcs(&big_u[row0 + j]);
    }

#pragma unroll
    for (int g = 0; g < GROUPS; ++g) {
        float4 r;
        r.x = sindy_row(v[g][0], c);
        r.y = sindy_row(v[g][1], c);
        r.z = sindy_row(v[g][2], c);
        r.w = sindy_row(v[g][3], c);
        int row0 = blk_row + g * (THREADS * ROWS_PER_GROUP) + threadIdx.x * ROWS_PER_GROUP;
        __stcs(&out4[row0 >> 2], r);
    }
}

// Guarded fallback for arbitrary n (scalar, simple).
__global__ void __launch_bounds__(THREADS)
sindy_kernel_guarded(const float4* __restrict__ big_u,
                     const float*  __restrict__ coeff,
                     const float*  __restrict__ base,
                     float*        __restrict__ out,
                     int start, int n) {
    float c[15];
    load_coeffs(coeff, base, c);
    int i = start + blockIdx.x * THREADS + threadIdx.x;
    if (i < n) {
        float4 v = __ldcs(&big_u[i]);
        __stcs(&out[i], sindy_row(v, c));
    }
}

extern "C" void kernel_launch(void* const* d_in, const int* in_sizes, int n_in,
                              void* d_out, int out_size) {
    const float4* big_u = (const float4*)d_in[0];   // [N,4] f32
    const float*  coeff = (const float*)d_in[1];    // [15]  f32
    const float*  base  = (const float*)d_in[2];    // [15]  f32
    float* out = (float*)d_out;                     // [N,1] f32

    int n = in_sizes[0] / 4;   // rows
    int n_full = n / CHUNK;    // full blocks

    if (n_full > 0)
        sindy_kernel_exact<<<n_full, THREADS>>>(big_u, coeff, base, (float4*)out);

    int tail_start = n_full * CHUNK;
    int tail = n - tail_start;
    if (tail > 0) {
        int tblocks = (tail + THREADS - 1) / THREADS;
        sindy_kernel_guarded<<<tblocks, THREADS>>>(big_u, coeff, base, out, tail_start, n);
    }
}

// round 6
// speedup vs baseline: 1.0560x; 1.0088x over previous
#include <cuda_runtime.h>

// Torch_SINDy streaming kernel, R6: persistent work-stealing + double-buffer.
// R3 (best 25.1us): one-shot, DRAM 75%, ~10% wave-tail idle + bursty per-warp
// load duty. R4 persistent regressed from phase-locked load/compute phases.
// R6: atomic chunk counter (no wave tail, natural stagger) + prefetch next
// chunk's loads before computing current (continuous MLP=4 per warp).

#define THREADS 256
#define ITEMS 4
#define CHUNK (THREADS * ITEMS)   // 1024 rows per chunk

__device__ unsigned int g_counter;

__global__ void reset_counter() { g_counter = 0u; }

__device__ __forceinline__ float sindy_row(float4 v, const float* c) {
    float u  = v.x;
    float u2 = u * u;
    float u3 = u2 * u;
    float y = v.y, z = v.z, w = v.w;
    float r = u * c[0] + u2 * c[1] + u3 * c[2]
            + y * c[3] + z * c[4] + w * c[5];
    r += y * (u * c[6]  + u2 * c[7]  + u3 * c[8]);
    r += z * (u * c[9]  + u2 * c[10] + u3 * c[11]);
    r += w * (u * c[12] + u2 * c[13] + u3 * c[14]);
    return r;
}

__device__ __forceinline__ void load_coeffs(const float* __restrict__ coeff,
                                            const float* __restrict__ base,
                                            float* c) {
    const float4* c4 = (const float4*)coeff;
    const float4* b4 = (const float4*)base;
#pragma unroll
    for (int q = 0; q < 3; ++q) {
        float4 cv = __ldg(&c4[q]);
        float4 bv = __ldg(&b4[q]);
        c[q*4+0] = cv.x * bv.x;
        c[q*4+1] = cv.y * bv.y;
        c[q*4+2] = cv.z * bv.z;
        c[q*4+3] = cv.w * bv.w;
    }
#pragma unroll
    for (int q = 12; q < 15; ++q)
        c[q] = __ldg(&coeff[q]) * __ldg(&base[q]);
}

__global__ void __launch_bounds__(THREADS, 4)
sindy_ws(const float4* __restrict__ big_u,
         const float*  __restrict__ coeff,
         const float*  __restrict__ base,
         float*        __restrict__ out,
         int n_chunks) {
    float c[15];
    load_coeffs(coeff, base, c);

    __shared__ unsigned int s_next[2];

    // Grab first chunk.
    if (threadIdx.x == 0) s_next[0] = atomicAdd(&g_counter, 1u);
    __syncthreads();
    unsigned int cur = s_next[0];
    if (cur >= (unsigned)n_chunks) return;

    int base_i = (int)cur * CHUNK + threadIdx.x;
    float4 va[ITEMS];
#pragma unroll
    for (int k = 0; k < ITEMS; ++k)
        va[k] = __ldcs(&big_u[base_i + k * THREADS]);

    int parity = 1;
    while (true) {
        // Grab + prefetch the next chunk BEFORE computing the current one,
        // so this warp always has loads in flight.
        if (threadIdx.x == 0) s_next[parity] = atomicAdd(&g_counter, 1u);
        __syncthreads();
        unsigned int nxt = s_next[parity];
        parity ^= 1;

        float4 vb[ITEMS];
        int next_base = (int)nxt * CHUNK + threadIdx.x;
        if (nxt < (unsigned)n_chunks) {
#pragma unroll
            for (int k = 0; k < ITEMS; ++k)
                vb[k] = __ldcs(&big_u[next_base + k * THREADS]);
        }

        // Compute + store current chunk (loads for next already issued).
#pragma unroll
        for (int k = 0; k < ITEMS; ++k)
            __stcs(&out[base_i + k * THREADS], sindy_row(va[k], c));

        if (nxt >= (unsigned)n_chunks) break;
        base_i = next_base;
#pragma unroll
        for (int k = 0; k < ITEMS; ++k)
            va[k] = vb[k];
    }
}

// Guarded tail for rows beyond the last full chunk.
__global__ void __launch_bounds__(THREADS)
sindy_tail(const float4* __restrict__ big_u,
           const float*  __restrict__ coeff,
           const float*  __restrict__ base,
           float*        __restrict__ out,
           int start, int n) {
    float c[15];
    load_coeffs(coeff, base, c);
    int i = start + blockIdx.x * THREADS + threadIdx.x;
    if (i < n) {
        float4 v = __ldcs(&big_u[i]);
        __stcs(&out[i], sindy_row(v, c));
    }
}

extern "C" void kernel_launch(void* const* d_in, const int* in_sizes, int n_in,
                              void* d_out, int out_size) {
    const float4* big_u = (const float4*)d_in[0];   // [N,4] f32
    const float*  coeff = (const float*)d_in[1];    // [15]  f32
    const float*  base  = (const float*)d_in[2];    // [15]  f32
    float* out = (float*)d_out;                     // [N,1] f32

    int n = in_sizes[0] / 4;   // rows
    int n_chunks = n / CHUNK;

    if (n_chunks > 0) {
        reset_counter<<<1, 1>>>();
        int grid = 152 * 4;                  // 4 blocks/SM resident
        if (grid > n_chunks) grid = n_chunks;
        sindy_ws<<<grid, THREADS>>>(big_u, coeff, base, out, n_chunks);
    }

    int tail_start = n_chunks * CHUNK;
    int tail = n - tail_start;
    if (tail > 0) {
        int tblocks = (tail + THREADS - 1) / THREADS;
        sindy_tail<<<tblocks, THREADS>>>(big_u, coeff, base, out, tail_start, n);
    }
}

// round 7
// speedup vs baseline: 1.2270x; 1.1620x over previous
#include <cuda_runtime.h>

// Torch_SINDy streaming kernel, R7.
// Evidence so far: one-shot + front-batched block-strided MLP=8 is the best
// structure (R3: 75% DRAM, 25.1us). Persistent variants (R4/R6) lose
// concurrency; consecutive-row packing (R5) breaks coalescing.
// R7 = R3 with 128-thread blocks: 8192 blocks -> ~2x finer wave granularity,
// smaller tail fraction, better SM packing. Per-thread shape unchanged.

#define ITEMS 8
#define THREADS 128
#define CHUNK (THREADS * ITEMS)   // 1024 rows per block

__device__ __forceinline__ float sindy_row(float4 v, const float* c) {
    float u  = v.x;
    float u2 = u * u;
    float u3 = u2 * u;
    float y = v.y, z = v.z, w = v.w;
    float r = u * c[0] + u2 * c[1] + u3 * c[2]
            + y * c[3] + z * c[4] + w * c[5];
    r += y * (u * c[6]  + u2 * c[7]  + u3 * c[8]);
    r += z * (u * c[9]  + u2 * c[10] + u3 * c[11]);
    r += w * (u * c[12] + u2 * c[13] + u3 * c[14]);
    return r;
}

__device__ __forceinline__ void load_coeffs(const float* __restrict__ coeff,
                                            const float* __restrict__ base,
                                            float* c) {
    const float4* c4 = (const float4*)coeff;
    const float4* b4 = (const float4*)base;
#pragma unroll
    for (int q = 0; q < 3; ++q) {
        float4 cv = __ldg(&c4[q]);
        float4 bv = __ldg(&b4[q]);
        c[q*4+0] = cv.x * bv.x;
        c[q*4+1] = cv.y * bv.y;
        c[q*4+2] = cv.z * bv.z;
        c[q*4+3] = cv.w * bv.w;
    }
#pragma unroll
    for (int q = 12; q < 15; ++q)
        c[q] = __ldg(&coeff[q]) * __ldg(&base[q]);
}

// Exact path: grid covers n exactly, no guards. 8 front-batched LDG.128
// (block-strided, fully coalesced), then 8 compute+store.
__global__ void __launch_bounds__(THREADS)
sindy_kernel_exact(const float4* __restrict__ big_u,
                   const float*  __restrict__ coeff,
                   const float*  __restrict__ base,
                   float*        __restrict__ out) {
    float c[15];
    load_coeffs(coeff, base, c);

    int base_i = blockIdx.x * CHUNK + threadIdx.x;

    float4 v[ITEMS];
#pragma unroll
    for (int k = 0; k < ITEMS; ++k)
        v[k] = __ldcs(&big_u[base_i + k * THREADS]);

#pragma unroll
    for (int k = 0; k < ITEMS; ++k)
        __stcs(&out[base_i + k * THREADS], sindy_row(v[k], c));
}

// Guarded tail for arbitrary n.
__global__ void __launch_bounds__(THREADS)
sindy_tail(const float4* __restrict__ big_u,
           const float*  __restrict__ coeff,
           const float*  __restrict__ base,
           float*        __restrict__ out,
           int start, int n) {
    float c[15];
    load_coeffs(coeff, base, c);
    int i = start + blockIdx.x * THREADS + threadIdx.x;
    if (i < n) {
        float4 v = __ldcs(&big_u[i]);
        __stcs(&out[i], sindy_row(v, c));
    }
}

extern "C" void kernel_launch(void* const* d_in, const int* in_sizes, int n_in,
                              void* d_out, int out_size) {
    const float4* big_u = (const float4*)d_in[0];   // [N,4] f32
    const float*  coeff = (const float*)d_in[1];    // [15]  f32
    const float*  base  = (const float*)d_in[2];    // [15]  f32
    float* out = (float*)d_out;                     // [N,1] f32

    int n = in_sizes[0] / 4;   // rows
    int n_full = n / CHUNK;

    if (n_full > 0)
        sindy_kernel_exact<<<n_full, THREADS>>>(big_u, coeff, base, out);

    int tail_start = n_full * CHUNK;
    int tail = n - tail_start;
    if (tail > 0) {
        int tblocks = (tail + THREADS - 1) / THREADS;
        sindy_tail<<<tblocks, THREADS>>>(big_u, coeff, base, out, tail_start, n);
    }
}